// round 7
// baseline (speedup 1.0000x reference)
#include <cuda_runtime.h>
#include <cuda_bf16.h>

#define B 8
#define C 256
#define HW 2304
#define DK 32
#define C2 512

// Scratch (device globals — no allocation allowed)
__device__ float g_vg[B * C];      // vg = Wv @ GvT
__device__ float g_wqk[B * C];     // wqk = kg @ Wq
__device__ float g_qb[B];          // qb = bq . kg
__device__ float g_lmax, g_lmin;   // reduced once from l

__device__ __forceinline__ float ex2f(float x) {
    float y;
    asm("ex2.approx.ftz.f32 %0, %1;" : "=f"(y) : "f"(x));
    return y;
}

__device__ __forceinline__ float warp_sum(float v) {
    #pragma unroll
    for (int o = 16; o; o >>= 1) v += __shfl_xor_sync(0xffffffffu, v, o);
    return v;
}

// ---------------------------------------------------------------------------
// Fused prep (p1 merged): per-batch text branch end-to-end.
//   t = text@Wg1+bg1 (float4 Wg1 loads, 4 c-groups x 128 j-quads)
//   -> LN -> exact GELU -> GvT = t@Wg2+bg2 -> vg = Wv@GvT, kg = Wk@GvT
//   -> wqk = kg@Wq, qb = bq.kg.
// grid = 9 blocks x 512 threads; block 8 reduces l -> g_lmax/g_lmin.
// ---------------------------------------------------------------------------
__global__ __launch_bounds__(512)
void prep_kernel(const float* __restrict__ text,
                 const float* __restrict__ Wg1,  const float* __restrict__ bg1,
                 const float* __restrict__ l,
                 const float* __restrict__ ln_g, const float* __restrict__ ln_b,
                 const float* __restrict__ Wg2,  const float* __restrict__ bg2,
                 const float* __restrict__ Wq,   const float* __restrict__ bq,
                 const float* __restrict__ Wk,   const float* __restrict__ Wv)
{
    const int tid = threadIdx.x;                 // 512 threads, 16 warps
    const int lane = tid & 31, wid = tid >> 5;

    if (blockIdx.x == 8) {
        // reduce l min/max
        __shared__ float rmx[16], rmn[16];
        float mx = -1e30f, mn = 1e30f;
        #pragma unroll
        for (int j = tid; j < HW; j += 512) {
            const float v = l[j];
            mx = fmaxf(mx, v);
            mn = fminf(mn, v);
        }
        #pragma unroll
        for (int o = 16; o; o >>= 1) {
            mx = fmaxf(mx, __shfl_xor_sync(0xffffffffu, mx, o));
            mn = fminf(mn, __shfl_xor_sync(0xffffffffu, mn, o));
        }
        if (lane == 0) { rmx[wid] = mx; rmn[wid] = mn; }
        __syncthreads();
        if (tid == 0) {
            float a = rmx[0], b2 = rmn[0];
            #pragma unroll
            for (int k = 1; k < 16; k++) { a = fmaxf(a, rmx[k]); b2 = fminf(b2, rmn[k]); }
            g_lmax = a; g_lmin = b2;
        }
        return;
    }

    const int b = blockIdx.x;

    __shared__ float text_s[C];
    __shared__ float4 part4[4][128];             // t partials over c-groups
    __shared__ float t_s[C2];
    __shared__ float gv_s[C];
    __shared__ float part_f[2048];               // 8 k-chunks x 256 c
    __shared__ float kg_s[DK];
    __shared__ float red[16];
    __shared__ float bcast[2];

    if (tid < C) text_s[tid] = text[b * C + tid];
    __syncthreads();

    // ---- t = text @ Wg1 + bg1 : thread = (c-group cg, j-quad jq) ----
    {
        const int jq = tid & 127;        // j = 4*jq .. 4*jq+3
        const int cg = tid >> 7;         // c in [cg*64, cg*64+64)
        const float4* W1 = (const float4*)Wg1;   // [256][128] float4
        float4 acc = make_float4(0.f, 0.f, 0.f, 0.f);
        #pragma unroll 16
        for (int cc = 0; cc < 64; cc++) {
            const int c = cg * 64 + cc;
            const float tk = text_s[c];
            const float4 w = W1[c * 128 + jq];
            acc.x = fmaf(tk, w.x, acc.x);
            acc.y = fmaf(tk, w.y, acc.y);
            acc.z = fmaf(tk, w.z, acc.z);
            acc.w = fmaf(tk, w.w, acc.w);
        }
        part4[cg][jq] = acc;
    }
    __syncthreads();
    if (tid < 128) {
        const float4 p0 = part4[0][tid], p1 = part4[1][tid];
        const float4 p2 = part4[2][tid], p3 = part4[3][tid];
        const float4 bb = ((const float4*)bg1)[tid];
        float4 r;
        r.x = p0.x + p1.x + p2.x + p3.x + bb.x;
        r.y = p0.y + p1.y + p2.y + p3.y + bb.y;
        r.z = p0.z + p1.z + p2.z + p3.z + bb.z;
        r.w = p0.w + p1.w + p2.w + p3.w + bb.w;
        ((float4*)t_s)[tid] = r;
    }
    __syncthreads();

    // ---- LayerNorm + exact GELU ----
    const float v = t_s[tid];
    float s1 = warp_sum(v);
    if (lane == 0) red[wid] = s1;
    __syncthreads();
    if (wid == 0) {
        float r = (lane < 16) ? red[lane] : 0.0f;
        r = warp_sum(r);
        if (lane == 0) bcast[0] = r * (1.0f / C2);
    }
    __syncthreads();
    const float mu = bcast[0];
    const float d = v - mu;
    float s2 = warp_sum(d * d);
    if (lane == 0) red[wid] = s2;
    __syncthreads();
    if (wid == 0) {
        float r = (lane < 16) ? red[lane] : 0.0f;
        r = warp_sum(r);
        if (lane == 0) bcast[1] = rsqrtf(r * (1.0f / C2) + 1e-5f);
    }
    __syncthreads();
    {
        float x = d * bcast[1] * ln_g[tid] + ln_b[tid];
        t_s[tid] = 0.5f * x * (1.0f + erff(x * 0.7071067811865476f));
    }
    __syncthreads();

    // ---- GvT[c] = sum_k t[k] * Wg2[k*C + c] + bg2[c]  (float4 over c) ----
    {
        const int q = tid & 63;       // c-group: c = 4q .. 4q+3
        const int h = tid >> 6;       // k-chunk: k in [h*64, h*64+64)
        const float4* W4 = (const float4*)Wg2;   // [512][64] float4
        float4 acc = make_float4(0.f, 0.f, 0.f, 0.f);
        #pragma unroll 16
        for (int kk = 0; kk < 64; kk++) {
            const int k = h * 64 + kk;
            const float tk = t_s[k];
            const float4 w = W4[k * 64 + q];
            acc.x = fmaf(tk, w.x, acc.x);
            acc.y = fmaf(tk, w.y, acc.y);
            acc.z = fmaf(tk, w.z, acc.z);
            acc.w = fmaf(tk, w.w, acc.w);
        }
        part_f[h * 256 + 4 * q + 0] = acc.x;
        part_f[h * 256 + 4 * q + 1] = acc.y;
        part_f[h * 256 + 4 * q + 2] = acc.z;
        part_f[h * 256 + 4 * q + 3] = acc.w;
    }
    __syncthreads();
    if (tid < C) {
        float g = bg2[tid];
        #pragma unroll
        for (int h = 0; h < 8; h++) g += part_f[h * 256 + tid];
        gv_s[tid] = g;
    }
    __syncthreads();

    // ---- vg[c] = Wv[c,:] . gv   (warp per output, 16 outputs/warp) ----
    {
        const float4* Wv4 = (const float4*)Wv;        // [256][64] float4
        const float4* gv4 = (const float4*)gv_s;
        const float4 gA = gv4[lane];
        const float4 gB = gv4[32 + lane];
        #pragma unroll
        for (int oo = 0; oo < 16; oo++) {
            const int c = wid * 16 + oo;
            const float4 wA = Wv4[c * 64 + lane];
            const float4 wB = Wv4[c * 64 + 32 + lane];
            float p = wA.x * gA.x + wA.y * gA.y + wA.z * gA.z + wA.w * gA.w
                    + wB.x * gB.x + wB.y * gB.y + wB.z * gB.z + wB.w * gB.w;
            p = warp_sum(p);
            if (lane == 0) g_vg[b * C + c] = p;
        }
        // ---- kg[d] = Wk[d,:] . gv   (2 outputs/warp) ----
        const float4* Wk4 = (const float4*)Wk;        // [32][64] float4
        #pragma unroll
        for (int oo = 0; oo < 2; oo++) {
            const int dd = wid * 2 + oo;
            const float4 wA = Wk4[dd * 64 + lane];
            const float4 wB = Wk4[dd * 64 + 32 + lane];
            float p = wA.x * gA.x + wA.y * gA.y + wA.z * gA.z + wA.w * gA.w
                    + wB.x * gB.x + wB.y * gB.y + wB.z * gB.z + wB.w * gB.w;
            p = warp_sum(p);
            if (lane == 0) kg_s[dd] = p;
        }
    }
    __syncthreads();

    // ---- wqk[c] = sum_d kg[d] * Wq[d*C + c];  qb = bq . kg ----
    if (tid < C) {
        float acc = 0.0f;
        #pragma unroll
        for (int dd = 0; dd < DK; dd++) acc = fmaf(kg_s[dd], Wq[dd * C + tid], acc);
        g_wqk[b * C + tid] = acc;
    }
    if (wid == 0) {
        float p = bq[lane] * kg_s[lane];
        p = warp_sum(p);
        if (lane == 0) g_qb[b] = p;
    }
}

// ---------------------------------------------------------------------------
// Attention with PDL: pre-sync region loads img (registers) + l (smem) —
// independent of prep — then cudaGridDependencySynchronize() before touching
// prep outputs. block = 256 thr = 8 warps; warp s = split s, lane = pixel.
// Thread owns channels [32s, 32s+32), img read ONCE. grid (72, 8).
// ---------------------------------------------------------------------------
__global__ __launch_bounds__(256, 3)
void attn_kernel(const float* __restrict__ img,
                 const float* __restrict__ l,
                 const float* __restrict__ bv,
                 const float* __restrict__ gamma_p,
                 float* __restrict__ out)
{
    const int b = blockIdx.y;
    const int tid = threadIdx.x;
    const int p = tid & 31;      // pixel within block (lane)
    const int s = tid >> 5;      // split 0..7 (warp)
    const int i = blockIdx.x * 32 + p;
    const int c0 = s * 32;

    __shared__ float ls[HW];
    __shared__ float wq[C];
    __shared__ float vgs[C];
    __shared__ float bvs[C];
    __shared__ float partA[256];
    __shared__ float partS[256];
    __shared__ float partT[256];

    // ---------- pre-sync: independent of prep ----------
    float im[32];
    const float* xb = img + (size_t)b * C * HW + (size_t)c0 * HW + i;
    #pragma unroll
    for (int cc = 0; cc < 32; cc++) im[cc] = xb[(size_t)cc * HW];

    #pragma unroll
    for (int j = tid; j < HW; j += 256) ls[j] = l[j];
    bvs[tid] = bv[tid];
    const float gm = *gamma_p;

    // ---------- wait for prep's global writes ----------
    cudaGridDependencySynchronize();

    const float qb   = g_qb[b];
    const float lmax = g_lmax;
    const float lmin = g_lmin;
    wq[tid]  = g_wqk[b * C + tid];
    vgs[tid] = g_vg[b * C + tid];
    __syncthreads();

    // partial dot over this thread's 32 channels
    float a = 0.0f;
    #pragma unroll
    for (int cc = 0; cc < 32; cc++) a = fmaf(wq[c0 + cc], im[cc], a);
    partA[tid] = a;
    __syncthreads();
    float af = qb;
    #pragma unroll
    for (int k = 0; k < 8; k++) af += partA[k * 32 + p];

    // softmax-weighted sum of l (rank-1 logits), exp2 domain, contiguous chunk
    const float al = af * 1.4426950408889634f;
    const float m2 = (al > 0.0f) ? al * lmax : al * lmin;
    float S = 0.0f, T = 0.0f;
    const int j0 = s * (HW / 8);
    #pragma unroll 8
    for (int jj = 0; jj < HW / 8; jj++) {
        const float lj = ls[j0 + jj];
        const float e = ex2f(fmaf(al, lj, -m2));
        S += e;
        T = fmaf(lj, e, T);
    }
    partS[tid] = S;
    partT[tid] = T;
    __syncthreads();
    float Ss = 0.0f, Ts = 0.0f;
    #pragma unroll
    for (int k = 0; k < 8; k++) {
        Ss += partS[k * 32 + p];
        Ts += partT[k * 32 + p];
    }
    const float sv = Ts / Ss;

    // out[b,c,i] = img + gamma * (vg[c]*sv + bv[c]) using register-cached img
    float* ob = out + (size_t)b * C * HW + (size_t)c0 * HW + i;
    #pragma unroll
    for (int cc = 0; cc < 32; cc++) {
        ob[(size_t)cc * HW] = fmaf(gm, fmaf(vgs[c0 + cc], sv, bvs[c0 + cc]), im[cc]);
    }
}

extern "C" void kernel_launch(void* const* d_in, const int* in_sizes, int n_in,
                              void* d_out, int out_size)
{
    const float* img   = (const float*)d_in[0];
    const float* text  = (const float*)d_in[1];
    const float* l     = (const float*)d_in[2];
    const float* Wg1   = (const float*)d_in[3];
    const float* bg1   = (const float*)d_in[4];
    const float* ln_g  = (const float*)d_in[5];
    const float* ln_b  = (const float*)d_in[6];
    const float* Wg2   = (const float*)d_in[7];
    const float* bg2   = (const float*)d_in[8];
    const float* Wq    = (const float*)d_in[9];
    const float* bq    = (const float*)d_in[10];
    const float* Wk    = (const float*)d_in[11];
    // d_in[12] = bk : cancels in softmax, unused
    const float* Wv    = (const float*)d_in[13];
    const float* bv    = (const float*)d_in[14];
    const float* gamma = (const float*)d_in[15];
    float* out = (float*)d_out;

    prep_kernel<<<B + 1, 512>>>(text, Wg1, bg1, l, ln_g, ln_b, Wg2, bg2,
                                Wq, bq, Wk, Wv);

    // attn with programmatic dependent launch: its pre-sync region (img + l
    // loads) overlaps prep; cudaGridDependencySynchronize() guards prep outputs.
    cudaLaunchConfig_t cfg = {};
    cfg.gridDim = dim3(HW / 32, B, 1);
    cfg.blockDim = dim3(256, 1, 1);
    cudaLaunchAttribute attr[1];
    attr[0].id = cudaLaunchAttributeProgrammaticStreamSerialization;
    attr[0].val.programmaticStreamSerializationAllowed = 1;
    cfg.attrs = attr;
    cfg.numAttrs = 1;
    cudaLaunchKernelEx(&cfg, attn_kernel, img, l, bv, gamma, out);
}

// round 8
// speedup vs baseline: 1.1280x; 1.1280x over previous
#include <cuda_runtime.h>
#include <cuda_bf16.h>

#define B 8
#define C 256
#define HW 2304
#define DK 32
#define C2 512

// Scratch (device globals — no allocation allowed)
__device__ float g_tp[8 * B * C2]; // p1 partials: [ct][b][j]
__device__ float g_vg[B * C];      // vg = Wv @ GvT
__device__ float g_wqk[B * C];     // wqk = kg @ Wq
__device__ float g_qb[B];          // qb = bq . kg
__device__ float g_lmax, g_lmin;   // reduced once from l

__device__ __forceinline__ float ex2f(float x) {
    float y;
    asm("ex2.approx.ftz.f32 %0, %1;" : "=f"(y) : "f"(x));
    return y;
}

__device__ __forceinline__ float warp_sum(float v) {
    #pragma unroll
    for (int o = 16; o; o >>= 1) v += __shfl_xor_sync(0xffffffffu, v, o);
    return v;
}

// packed f32x2 helpers (sm_100a: FFMA2 only reachable via PTX f32x2)
__device__ __forceinline__ unsigned long long pack2(float lo, float hi) {
    unsigned long long r;
    asm("mov.b64 %0, {%1, %2};" : "=l"(r) : "f"(lo), "f"(hi));
    return r;
}
__device__ __forceinline__ void unpack2(unsigned long long v, float& lo, float& hi) {
    asm("mov.b64 {%0, %1}, %2;" : "=f"(lo), "=f"(hi) : "l"(v));
}
__device__ __forceinline__ unsigned long long fma2(unsigned long long a,
                                                   unsigned long long b,
                                                   unsigned long long c) {
    unsigned long long d;
    asm("fma.rn.f32x2 %0, %1, %2, %3;" : "=l"(d) : "l"(a), "l"(b), "l"(c));
    return d;
}
__device__ __forceinline__ unsigned long long add2(unsigned long long a,
                                                   unsigned long long b) {
    unsigned long long d;
    asm("add.rn.f32x2 %0, %1, %2;" : "=l"(d) : "l"(a), "l"(b));
    return d;
}

// ---------------------------------------------------------------------------
// P1: partial t = text @ Wg1 over a 32-channel tile. grid 129 x 256.
// blocks 0..127: b(8) x jhalf(2) x ctile(8); block 128: l min/max.
// ---------------------------------------------------------------------------
__global__ __launch_bounds__(256)
void p1_kernel(const float* __restrict__ text,
               const float* __restrict__ Wg1,
               const float* __restrict__ l)
{
    const int tid = threadIdx.x;
    const int blk = blockIdx.x;

    if (blk == 128) {
        __shared__ float rmx[8], rmn[8];
        float mx = -1e30f, mn = 1e30f;
        #pragma unroll
        for (int j = tid; j < HW; j += 256) {
            const float v = l[j];
            mx = fmaxf(mx, v);
            mn = fminf(mn, v);
        }
        #pragma unroll
        for (int o = 16; o; o >>= 1) {
            mx = fmaxf(mx, __shfl_xor_sync(0xffffffffu, mx, o));
            mn = fminf(mn, __shfl_xor_sync(0xffffffffu, mn, o));
        }
        if ((tid & 31) == 0) { rmx[tid >> 5] = mx; rmn[tid >> 5] = mn; }
        __syncthreads();
        if (tid == 0) {
            float a = rmx[0], b2 = rmn[0];
            #pragma unroll
            for (int k = 1; k < 8; k++) { a = fmaxf(a, rmx[k]); b2 = fminf(b2, rmn[k]); }
            g_lmax = a; g_lmin = b2;
        }
        return;
    }

    const int b  = blk >> 4;
    const int jh = (blk >> 3) & 1;
    const int ct = blk & 7;
    const int j  = jh * 256 + tid;

    __shared__ float text_s[32];
    if (tid < 32) text_s[tid] = text[b * C + ct * 32 + tid];
    __syncthreads();

    float acc = 0.0f;
    #pragma unroll
    for (int cc = 0; cc < 32; cc++) {
        acc = fmaf(text_s[cc], Wg1[(ct * 32 + cc) * C2 + j], acc);
    }
    g_tp[ct * (B * C2) + b * C2 + j] = acc;
}

// ---------------------------------------------------------------------------
// Fused prep: combine p1 partials + bias, LN + GELU, GvT = t@Wg2+bg2,
// vg = Wv@GvT, kg = Wk@GvT, wqk = kg@Wq, qb = bq.kg.
// One block per batch, 512 threads.
// ---------------------------------------------------------------------------
__global__ __launch_bounds__(512)
void prep_kernel(const float* __restrict__ bg1,
                 const float* __restrict__ ln_g, const float* __restrict__ ln_b,
                 const float* __restrict__ Wg2,  const float* __restrict__ bg2,
                 const float* __restrict__ Wq,   const float* __restrict__ bq,
                 const float* __restrict__ Wk,   const float* __restrict__ Wv)
{
    const int b = blockIdx.x;
    const int tid = threadIdx.x;                 // 512 threads, 16 warps
    const int lane = tid & 31, wid = tid >> 5;

    __shared__ float t_s[C2];
    __shared__ float gv_s[C];
    __shared__ float part_f[2048];               // 8 k-chunks x 256 c
    __shared__ float kg_s[DK];
    __shared__ float red[16];
    __shared__ float bcast[2];

    // ---- combine p1 partials (fixed order: deterministic) ----
    float v = bg1[tid];
    #pragma unroll
    for (int ct = 0; ct < 8; ct++) v += g_tp[ct * (B * C2) + b * C2 + tid];

    // ---- LayerNorm + exact GELU ----
    float s1 = warp_sum(v);
    if (lane == 0) red[wid] = s1;
    __syncthreads();
    if (wid == 0) {
        float r = (lane < 16) ? red[lane] : 0.0f;
        r = warp_sum(r);
        if (lane == 0) bcast[0] = r * (1.0f / C2);
    }
    __syncthreads();
    const float mu = bcast[0];
    const float d = v - mu;
    float s2 = warp_sum(d * d);
    if (lane == 0) red[wid] = s2;
    __syncthreads();
    if (wid == 0) {
        float r = (lane < 16) ? red[lane] : 0.0f;
        r = warp_sum(r);
        if (lane == 0) bcast[1] = rsqrtf(r * (1.0f / C2) + 1e-5f);
    }
    __syncthreads();
    {
        float x = d * bcast[1] * ln_g[tid] + ln_b[tid];
        t_s[tid] = 0.5f * x * (1.0f + erff(x * 0.7071067811865476f));
    }
    __syncthreads();

    // ---- GvT[c] = sum_k t[k] * Wg2[k*C + c] + bg2[c]  (float4 over c) ----
    {
        const int q = tid & 63;       // c-group: c = 4q .. 4q+3
        const int h = tid >> 6;       // k-chunk: k in [h*64, h*64+64)
        const float4* W4 = (const float4*)Wg2;   // [512][64] float4
        float4 acc = make_float4(0.f, 0.f, 0.f, 0.f);
        #pragma unroll 16
        for (int kk = 0; kk < 64; kk++) {
            const int k = h * 64 + kk;
            const float tk = t_s[k];
            const float4 w = W4[k * 64 + q];
            acc.x = fmaf(tk, w.x, acc.x);
            acc.y = fmaf(tk, w.y, acc.y);
            acc.z = fmaf(tk, w.z, acc.z);
            acc.w = fmaf(tk, w.w, acc.w);
        }
        part_f[h * 256 + 4 * q + 0] = acc.x;
        part_f[h * 256 + 4 * q + 1] = acc.y;
        part_f[h * 256 + 4 * q + 2] = acc.z;
        part_f[h * 256 + 4 * q + 3] = acc.w;
    }
    __syncthreads();
    if (tid < C) {
        float g = bg2[tid];
        #pragma unroll
        for (int h = 0; h < 8; h++) g += part_f[h * 256 + tid];
        gv_s[tid] = g;
    }
    __syncthreads();

    // ---- vg[c] = Wv[c,:] . gv   (warp per output, 16 outputs/warp) ----
    {
        const float4* Wv4 = (const float4*)Wv;        // [256][64] float4
        const float4* gv4 = (const float4*)gv_s;
        const float4 gA = gv4[lane];
        const float4 gB = gv4[32 + lane];
        #pragma unroll
        for (int oo = 0; oo < 16; oo++) {
            const int c = wid * 16 + oo;
            const float4 wA = Wv4[c * 64 + lane];
            const float4 wB = Wv4[c * 64 + 32 + lane];
            float p = wA.x * gA.x + wA.y * gA.y + wA.z * gA.z + wA.w * gA.w
                    + wB.x * gB.x + wB.y * gB.y + wB.z * gB.z + wB.w * gB.w;
            p = warp_sum(p);
            if (lane == 0) g_vg[b * C + c] = p;
        }
        // ---- kg[d] = Wk[d,:] . gv   (2 outputs/warp) ----
        const float4* Wk4 = (const float4*)Wk;        // [32][64] float4
        #pragma unroll
        for (int oo = 0; oo < 2; oo++) {
            const int dd = wid * 2 + oo;
            const float4 wA = Wk4[dd * 64 + lane];
            const float4 wB = Wk4[dd * 64 + 32 + lane];
            float p = wA.x * gA.x + wA.y * gA.y + wA.z * gA.z + wA.w * gA.w
                    + wB.x * gB.x + wB.y * gB.y + wB.z * gB.z + wB.w * gB.w;
            p = warp_sum(p);
            if (lane == 0) kg_s[dd] = p;
        }
    }
    __syncthreads();

    // ---- wqk[c] = sum_d kg[d] * Wq[d*C + c];  qb = bq . kg ----
    if (tid < C) {
        float acc = 0.0f;
        #pragma unroll
        for (int dd = 0; dd < DK; dd++) acc = fmaf(kg_s[dd], Wq[dd * C + tid], acc);
        g_wqk[b * C + tid] = acc;
    }
    if (wid == 0) {
        float p = bq[lane] * kg_s[lane];
        p = warp_sum(p);
        if (lane == 0) g_qb[b] = p;
    }
}

// ---------------------------------------------------------------------------
// Attention: block = 256 thr = 8 warps; warp s = split s, lane = pixel.
// Thread owns channels [32s, 32s+32), img read ONCE (registers).
// occ-4 (one wave: 576 blocks <= 4*148) + f32x2-packed exp loop.
// grid (72, 8).
// ---------------------------------------------------------------------------
__global__ __launch_bounds__(256, 4)
void attn_kernel(const float* __restrict__ img,
                 const float* __restrict__ l,
                 const float* __restrict__ bv,
                 const float* __restrict__ gamma_p,
                 float* __restrict__ out)
{
    const int b = blockIdx.y;
    const int tid = threadIdx.x;
    const int p = tid & 31;      // pixel within block (lane)
    const int s = tid >> 5;      // split 0..7 (warp)
    const int i = blockIdx.x * 32 + p;
    const int c0 = s * 32;

    __shared__ float2 ls2[HW / 2];
    __shared__ float wq[C];
    __shared__ float vgs[C];
    __shared__ float bvs[C];
    __shared__ float partA[256];
    __shared__ float partS[256];
    __shared__ float partT[256];

    // front-batch img loads (32 contiguous channels per thread) into registers
    float im[32];
    const float* xb = img + (size_t)b * C * HW + (size_t)c0 * HW + i;
    #pragma unroll
    for (int cc = 0; cc < 32; cc++) im[cc] = xb[(size_t)cc * HW];

    const float gm   = *gamma_p;
    const float qb   = g_qb[b];
    const float lmax = g_lmax;
    const float lmin = g_lmin;

    // smem fills overlap the in-flight img loads
    {
        float* lsf = (float*)ls2;
        #pragma unroll
        for (int j = tid; j < HW; j += 256) lsf[j] = l[j];
    }
    wq[tid]  = g_wqk[b * C + tid];
    vgs[tid] = g_vg[b * C + tid];
    bvs[tid] = bv[tid];
    __syncthreads();

    // partial dot over this thread's 32 channels
    float a = 0.0f;
    #pragma unroll
    for (int cc = 0; cc < 32; cc++) a = fmaf(wq[c0 + cc], im[cc], a);
    partA[tid] = a;
    __syncthreads();
    float af = qb;
    #pragma unroll
    for (int k = 0; k < 8; k++) af += partA[k * 32 + p];

    // softmax-weighted sum of l (rank-1 logits), exp2 domain,
    // contiguous j chunk of 288 processed as 144 packed f32x2 pairs
    const float al = af * 1.4426950408889634f;
    const float m2 = (al > 0.0f) ? al * lmax : al * lmin;
    const unsigned long long al2  = pack2(al, al);
    const unsigned long long m2n2 = pack2(-m2, -m2);
    unsigned long long S2 = pack2(0.0f, 0.0f);
    unsigned long long T2 = S2;
    const int base2 = s * (HW / 16);   // float2 index of this split's chunk
    #pragma unroll 8
    for (int jj = 0; jj < HW / 16; jj++) {
        const float2 lj2f = ls2[base2 + jj];
        const unsigned long long lj2 = pack2(lj2f.x, lj2f.y);
        const unsigned long long u2 = fma2(al2, lj2, m2n2);
        float u0, u1;
        unpack2(u2, u0, u1);
        const unsigned long long e2 = pack2(ex2f(u0), ex2f(u1));
        S2 = add2(S2, e2);
        T2 = fma2(lj2, e2, T2);
    }
    float S0, S1, T0, T1;
    unpack2(S2, S0, S1);
    unpack2(T2, T0, T1);
    partS[tid] = S0 + S1;
    partT[tid] = T0 + T1;
    __syncthreads();
    float Ss = 0.0f, Ts = 0.0f;
    #pragma unroll
    for (int k = 0; k < 8; k++) {
        Ss += partS[k * 32 + p];
        Ts += partT[k * 32 + p];
    }
    const float sv = Ts / Ss;

    // out[b,c,i] = img + gamma * (vg[c]*sv + bv[c]) using register-cached img
    float* ob = out + (size_t)b * C * HW + (size_t)c0 * HW + i;
    #pragma unroll
    for (int cc = 0; cc < 32; cc++) {
        ob[(size_t)cc * HW] = fmaf(gm, fmaf(vgs[c0 + cc], sv, bvs[c0 + cc]), im[cc]);
    }
}

extern "C" void kernel_launch(void* const* d_in, const int* in_sizes, int n_in,
                              void* d_out, int out_size)
{
    const float* img   = (const float*)d_in[0];
    const float* text  = (const float*)d_in[1];
    const float* l     = (const float*)d_in[2];
    const float* Wg1   = (const float*)d_in[3];
    const float* bg1   = (const float*)d_in[4];
    const float* ln_g  = (const float*)d_in[5];
    const float* ln_b  = (const float*)d_in[6];
    const float* Wg2   = (const float*)d_in[7];
    const float* bg2   = (const float*)d_in[8];
    const float* Wq    = (const float*)d_in[9];
    const float* bq    = (const float*)d_in[10];
    const float* Wk    = (const float*)d_in[11];
    // d_in[12] = bk : cancels in softmax, unused
    const float* Wv    = (const float*)d_in[13];
    const float* bv    = (const float*)d_in[14];
    const float* gamma = (const float*)d_in[15];
    float* out = (float*)d_out;

    p1_kernel<<<129, 256>>>(text, Wg1, l);
    prep_kernel<<<B, 512>>>(bg1, ln_g, ln_b, Wg2, bg2, Wq, bq, Wk, Wv);
    dim3 grid(HW / 32, B);
    attn_kernel<<<grid, 256>>>(img, l, bv, gamma, out);
}